// round 1
// baseline (speedup 1.0000x reference)
#include <cuda_runtime.h>
#include <math.h>

#define N_TOTAL 102400
#define E_TOTAL 4096000
#define F 256
#define NODES_PER_G 400
#define NUM_G 256

// ---------------- scratch (device globals; no allocation allowed) -----------
__device__ int   g_deg[N_TOTAL];
__device__ int   g_cursor[N_TOTAL];
__device__ int   g_rowptr[N_TOTAL + 1];
__device__ int   g_col[E_TOTAL];
__device__ float g_dis[N_TOTAL];
__device__ float g_hp[(size_t)N_TOTAL * F];   // ~105 MB
__device__ float g_buf[(size_t)N_TOTAL * F];  // ~105 MB
__device__ int   g_is64;

// ---------------- setup kernels --------------------------------------------
__global__ void init_kernel() {
    int i = blockIdx.x * blockDim.x + threadIdx.x;
    if (i < N_TOTAL) { g_deg[i] = 1; g_cursor[i] = 0; }  // deg starts at 1 (self loop)
}

// Detect whether edge_index is int64 (JAX x64) or int32 (JAX default).
// Values are in [0, 102400) < 2^31, so for int64 data every odd 32-bit word is 0.
__global__ void detect_kernel(const unsigned int* __restrict__ w) {
    __shared__ int any;
    if (threadIdx.x == 0) any = 0;
    __syncthreads();
    int idx = 1 + 2 * (int)threadIdx.x;   // odd words 1..2047
    if (w[idx] != 0u) atomicOr(&any, 1);
    __syncthreads();
    if (threadIdx.x == 0) g_is64 = (any ? 0 : 1);
}

__device__ __forceinline__ int load_idx(const void* ei, long long pos) {
    if (g_is64) return (int)((const long long*)ei)[pos];
    return ((const int*)ei)[pos];
}

__global__ void count_kernel(const void* __restrict__ ei) {
    int e = blockIdx.x * blockDim.x + threadIdx.x;
    if (e >= E_TOTAL) return;
    int dst = load_idx(ei, (long long)E_TOTAL + e);
    atomicAdd(&g_deg[dst], 1);
}

__global__ void dis_kernel() {
    int i = blockIdx.x * blockDim.x + threadIdx.x;
    if (i < N_TOTAL) g_dis[i] = rsqrtf((float)g_deg[i]);
}

// Single-CTA exclusive scan of (deg-1) -> rowptr. N_TOTAL = 100 * 1024 exactly.
__global__ void scan_kernel() {
    __shared__ int s[1024];
    __shared__ int carry_s;
    int tid = threadIdx.x;
    if (tid == 0) carry_s = 0;
    __syncthreads();
    for (int base = 0; base < N_TOTAL; base += 1024) {
        int i = base + tid;
        int v = g_deg[i] - 1;
        s[tid] = v;
        __syncthreads();
        for (int off = 1; off < 1024; off <<= 1) {
            int t = 0;
            if (tid >= off) t = s[tid - off];
            __syncthreads();
            s[tid] += t;
            __syncthreads();
        }
        int carry = carry_s;
        g_rowptr[i] = carry + s[tid] - v;   // exclusive
        int tot = s[1023];
        __syncthreads();
        if (tid == 0) carry_s = carry + tot;
        __syncthreads();
    }
    if (tid == 0) g_rowptr[N_TOTAL] = carry_s;
}

__global__ void fill_kernel(const void* __restrict__ ei) {
    int e = blockIdx.x * blockDim.x + threadIdx.x;
    if (e >= E_TOTAL) return;
    int src = load_idx(ei, e);
    int dst = load_idx(ei, (long long)E_TOTAL + e);
    int p = atomicAdd(&g_cursor[dst], 1);
    g_col[g_rowptr[dst] + p] = src;
}

// ---------------- SGEMM: out[m,n] = dis[m] * (A[m,:K] @ W[:K,n]) ------------
// BM=128, BN=128, BK=8, 256 threads, 8x8 per thread. M,N,K all divide tiles.
__global__ __launch_bounds__(256) void gemm_scaled_kernel(
    const float* __restrict__ A, const float* __restrict__ W,
    float* __restrict__ out, int K)
{
    __shared__ __align__(16) float As[8][128];
    __shared__ __align__(16) float Bs[8][128];
    int tid = threadIdx.x;
    int m0 = blockIdx.y * 128, n0 = blockIdx.x * 128;
    int arow = tid >> 1, aq = (tid & 1) * 4;
    int brow = tid >> 5, bcol = (tid & 31) * 4;
    int tx = tid & 15, ty = tid >> 4;

    float acc[8][8];
#pragma unroll
    for (int i = 0; i < 8; i++)
#pragma unroll
        for (int j = 0; j < 8; j++) acc[i][j] = 0.f;

    for (int kk = 0; kk < K; kk += 8) {
        float4 av = *(const float4*)&A[(size_t)(m0 + arow) * K + kk + aq];
        As[aq + 0][arow] = av.x; As[aq + 1][arow] = av.y;
        As[aq + 2][arow] = av.z; As[aq + 3][arow] = av.w;
        *(float4*)&Bs[brow][bcol] =
            *(const float4*)&W[(size_t)(kk + brow) * F + n0 + bcol];
        __syncthreads();
#pragma unroll
        for (int k = 0; k < 8; k++) {
            float4 a0 = *(const float4*)&As[k][ty * 8];
            float4 a1 = *(const float4*)&As[k][ty * 8 + 4];
            float4 b0 = *(const float4*)&Bs[k][tx * 8];
            float4 b1 = *(const float4*)&Bs[k][tx * 8 + 4];
            float a[8] = {a0.x, a0.y, a0.z, a0.w, a1.x, a1.y, a1.z, a1.w};
            float b[8] = {b0.x, b0.y, b0.z, b0.w, b1.x, b1.y, b1.z, b1.w};
#pragma unroll
            for (int i = 0; i < 8; i++)
#pragma unroll
                for (int j = 0; j < 8; j++) acc[i][j] += a[i] * b[j];
        }
        __syncthreads();
    }

#pragma unroll
    for (int i = 0; i < 8; i++) {
        int m = m0 + ty * 8 + i;
        float d = g_dis[m];
        float4 o0 = make_float4(d * acc[i][0], d * acc[i][1], d * acc[i][2], d * acc[i][3]);
        float4 o1 = make_float4(d * acc[i][4], d * acc[i][5], d * acc[i][6], d * acc[i][7]);
        *(float4*)&out[(size_t)m * F + n0 + tx * 8]     = o0;
        *(float4*)&out[(size_t)m * F + n0 + tx * 8 + 4] = o1;
    }
}

// ---------------- Aggregation: warp per destination node --------------------
// out[dst] = act( dis[dst] * (sum_{src in N(dst)} hp[src] + hp[dst]) + bias )
__global__ __launch_bounds__(256) void agg_kernel(
    const float* __restrict__ hp, const float* __restrict__ bias,
    float* __restrict__ out, int relu)
{
    int warp = (blockIdx.x * blockDim.x + threadIdx.x) >> 5;
    if (warp >= N_TOTAL) return;
    int lane = threadIdx.x & 31;
    const float4* hp4 = (const float4*)hp;
    int dst = warp;

    float4 acc0 = hp4[(size_t)dst * 64 + lane];        // feats [lane*4 .. +3]
    float4 acc1 = hp4[(size_t)dst * 64 + 32 + lane];   // feats [128+lane*4 ..]

    int e = g_rowptr[dst], end = g_rowptr[dst + 1];
    for (; e + 1 < end; e += 2) {
        int s0 = g_col[e], s1 = g_col[e + 1];
        float4 v00 = hp4[(size_t)s0 * 64 + lane];
        float4 v01 = hp4[(size_t)s0 * 64 + 32 + lane];
        float4 v10 = hp4[(size_t)s1 * 64 + lane];
        float4 v11 = hp4[(size_t)s1 * 64 + 32 + lane];
        acc0.x += v00.x + v10.x; acc0.y += v00.y + v10.y;
        acc0.z += v00.z + v10.z; acc0.w += v00.w + v10.w;
        acc1.x += v01.x + v11.x; acc1.y += v01.y + v11.y;
        acc1.z += v01.z + v11.z; acc1.w += v01.w + v11.w;
    }
    if (e < end) {
        int s0 = g_col[e];
        float4 v00 = hp4[(size_t)s0 * 64 + lane];
        float4 v01 = hp4[(size_t)s0 * 64 + 32 + lane];
        acc0.x += v00.x; acc0.y += v00.y; acc0.z += v00.z; acc0.w += v00.w;
        acc1.x += v01.x; acc1.y += v01.y; acc1.z += v01.z; acc1.w += v01.w;
    }

    float d = g_dis[dst];
    const float4* b4 = (const float4*)bias;
    float4 b0 = b4[lane], b1 = b4[32 + lane];
    float4 r0 = make_float4(d * acc0.x + b0.x, d * acc0.y + b0.y,
                            d * acc0.z + b0.z, d * acc0.w + b0.w);
    float4 r1 = make_float4(d * acc1.x + b1.x, d * acc1.y + b1.y,
                            d * acc1.z + b1.z, d * acc1.w + b1.w);
    if (relu) {
        r0.x = fmaxf(r0.x, 0.f); r0.y = fmaxf(r0.y, 0.f);
        r0.z = fmaxf(r0.z, 0.f); r0.w = fmaxf(r0.w, 0.f);
        r1.x = fmaxf(r1.x, 0.f); r1.y = fmaxf(r1.y, 0.f);
        r1.z = fmaxf(r1.z, 0.f); r1.w = fmaxf(r1.w, 0.f);
    }
    float4* o4 = (float4*)out;
    o4[(size_t)dst * 64 + lane]      = r0;
    o4[(size_t)dst * 64 + 32 + lane] = r1;
}

// ---------------- readout (meanmax) + final linear, one CTA per graph -------
__global__ __launch_bounds__(256) void readout_kernel(
    const float* __restrict__ h, const float* __restrict__ Wm,
    const float* __restrict__ bm, float* __restrict__ out)
{
    int g = blockIdx.x;
    int t = threadIdx.x;   // 256 threads = one per feature
    const float* base = h + (size_t)g * NODES_PER_G * F;
    float s = 0.f, mx = -INFINITY;
    for (int i = 0; i < NODES_PER_G; i++) {
        float v = base[(size_t)i * F + t];
        s += v;
        mx = fmaxf(mx, v);
    }
    __shared__ float gf[2 * F];
    gf[t]     = s * (1.0f / NODES_PER_G);
    gf[F + t] = mx;
    __syncthreads();

    float p0 = gf[t] * Wm[t * 2 + 0] + gf[F + t] * Wm[(F + t) * 2 + 0];
    float p1 = gf[t] * Wm[t * 2 + 1] + gf[F + t] * Wm[(F + t) * 2 + 1];
    __shared__ float r0[256], r1[256];
    r0[t] = p0; r1[t] = p1;
    __syncthreads();
    for (int off = 128; off > 0; off >>= 1) {
        if (t < off) { r0[t] += r0[t + off]; r1[t] += r1[t + off]; }
        __syncthreads();
    }
    if (t == 0) {
        out[g * 2 + 0] = r0[0] + bm[0];
        out[g * 2 + 1] = r1[0] + bm[1];
    }
}

// ---------------- launcher --------------------------------------------------
extern "C" void kernel_launch(void* const* d_in, const int* in_sizes, int n_in,
                              void* d_out, int out_size)
{
    // Input order: x, edge_index, batch, [num_graphs], W1, b1, W2, b2, Wm, bm
    int base = (in_sizes[3] == 1) ? 4 : 3;
    const float* x  = (const float*)d_in[0];
    const void*  ei = d_in[1];
    const float* W1 = (const float*)d_in[base + 0];
    const float* b1 = (const float*)d_in[base + 1];
    const float* W2 = (const float*)d_in[base + 2];
    const float* b2 = (const float*)d_in[base + 3];
    const float* Wm = (const float*)d_in[base + 4];
    const float* bm = (const float*)d_in[base + 5];
    float* out = (float*)d_out;

    float *hp = nullptr, *buf = nullptr;
    cudaGetSymbolAddress((void**)&hp,  g_hp);
    cudaGetSymbolAddress((void**)&buf, g_buf);

    const int TB = 256;
    init_kernel<<<(N_TOTAL + TB - 1) / TB, TB>>>();
    detect_kernel<<<1, 1024>>>((const unsigned int*)ei);
    count_kernel<<<(E_TOTAL + TB - 1) / TB, TB>>>(ei);
    dis_kernel<<<(N_TOTAL + TB - 1) / TB, TB>>>();
    scan_kernel<<<1, 1024>>>();
    fill_kernel<<<(E_TOTAL + TB - 1) / TB, TB>>>(ei);

    dim3 gg(F / 128, N_TOTAL / 128);
    // layer 1: hp = dis * (x @ W1)
    gemm_scaled_kernel<<<gg, 256>>>(x, W1, hp, 400);
    // agg1: buf = relu(dis*(sum hp) + b1)
    agg_kernel<<<N_TOTAL / 8, 256>>>(hp, b1, buf, 1);
    // layer 2: hp = dis * (buf @ W2)
    gemm_scaled_kernel<<<gg, 256>>>(buf, W2, hp, 256);
    // agg2: buf = dis*(sum hp) + b2
    agg_kernel<<<N_TOTAL / 8, 256>>>(hp, b2, buf, 0);
    // readout + final linear
    readout_kernel<<<NUM_G, 256>>>(buf, Wm, bm, out);
}

// round 3
// speedup vs baseline: 1.0310x; 1.0310x over previous
#include <cuda_runtime.h>
#include <math.h>

#define N_TOTAL 102400
#define E_TOTAL 4096000
#define F 256
#define NODES_PER_G 400
#define NUM_G 256

// ---------------- scratch (device globals; no allocation allowed) -----------
__device__ int   g_deg[N_TOTAL];
__device__ int   g_cursor[N_TOTAL];
__device__ int   g_rowptr[N_TOTAL + 1];
__device__ int   g_col[E_TOTAL];
__device__ float g_dis[N_TOTAL];
__device__ float g_hp[(size_t)N_TOTAL * F];   // ~105 MB
__device__ float g_buf[(size_t)N_TOTAL * F];  // ~105 MB
__device__ int   g_is64;

// ---------------- f32x2 packed-FMA helpers (FFMA2: 2 fp32 FMA per issue) ----
__device__ __forceinline__ unsigned long long pack2_dup(float v) {
    unsigned long long r;
    asm("mov.b64 %0, {%1, %1};" : "=l"(r) : "f"(v));
    return r;
}
__device__ __forceinline__ unsigned long long ffma2(
    unsigned long long a, unsigned long long b, unsigned long long c) {
    unsigned long long d;
    asm("fma.rn.f32x2 %0, %1, %2, %3;" : "=l"(d) : "l"(a), "l"(b), "l"(c));
    return d;
}
__device__ __forceinline__ float2 unpack2(unsigned long long v) {
    float2 f;
    asm("mov.b64 {%0, %1}, %2;" : "=f"(f.x), "=f"(f.y) : "l"(v));
    return f;
}
__device__ __forceinline__ void cp_async16(void* smem_dst, const void* gmem_src) {
    unsigned long long sa = __cvta_generic_to_shared(smem_dst);
    asm volatile("cp.async.cg.shared.global [%0], [%1], 16;"
                 :: "l"(sa), "l"(gmem_src) : "memory");
}

// ---------------- setup kernels --------------------------------------------
__global__ void init_kernel() {
    int i = blockIdx.x * blockDim.x + threadIdx.x;
    if (i < N_TOTAL) { g_deg[i] = 1; g_cursor[i] = 0; }  // deg starts at 1 (self loop)
}

// Detect whether edge_index is int64 (JAX x64) or int32 (JAX default).
// Values are in [0, 102400) < 2^31, so for int64 data every odd 32-bit word is 0.
__global__ void detect_kernel(const unsigned int* __restrict__ w) {
    __shared__ int any;
    if (threadIdx.x == 0) any = 0;
    __syncthreads();
    int idx = 1 + 2 * (int)threadIdx.x;   // odd words 1..2047
    if (w[idx] != 0u) atomicOr(&any, 1);
    __syncthreads();
    if (threadIdx.x == 0) g_is64 = (any ? 0 : 1);
}

__device__ __forceinline__ int load_idx(const void* ei, long long pos) {
    if (g_is64) return (int)((const long long*)ei)[pos];
    return ((const int*)ei)[pos];
}

__global__ void count_kernel(const void* __restrict__ ei) {
    int e = blockIdx.x * blockDim.x + threadIdx.x;
    if (e >= E_TOTAL) return;
    int dst = load_idx(ei, (long long)E_TOTAL + e);
    atomicAdd(&g_deg[dst], 1);
}

// Single-CTA exclusive scan of (deg-1) -> rowptr, fused with dis=rsqrt(deg).
__global__ void scan_dis_kernel() {
    __shared__ int s[1024];
    __shared__ int carry_s;
    int tid = threadIdx.x;
    if (tid == 0) carry_s = 0;
    __syncthreads();
    for (int base = 0; base < N_TOTAL; base += 1024) {
        int i = base + tid;
        int d = g_deg[i];
        g_dis[i] = rsqrtf((float)d);
        int v = d - 1;
        s[tid] = v;
        __syncthreads();
        for (int off = 1; off < 1024; off <<= 1) {
            int t = 0;
            if (tid >= off) t = s[tid - off];
            __syncthreads();
            s[tid] += t;
            __syncthreads();
        }
        int carry = carry_s;
        g_rowptr[i] = carry + s[tid] - v;   // exclusive
        int tot = s[1023];
        __syncthreads();
        if (tid == 0) carry_s = carry + tot;
        __syncthreads();
    }
    if (tid == 0) g_rowptr[N_TOTAL] = carry_s;
}

__global__ void fill_kernel(const void* __restrict__ ei) {
    int e = blockIdx.x * blockDim.x + threadIdx.x;
    if (e >= E_TOTAL) return;
    int src = load_idx(ei, e);
    int dst = load_idx(ei, (long long)E_TOTAL + e);
    int p = atomicAdd(&g_cursor[dst], 1);
    g_col[g_rowptr[dst] + p] = src;
}

// ---------------- SGEMM (pure): out = A @ W  -------------------------------
// BM=128, BN=128, BK=8, 256 threads, 8x8 per thread via f32x2 packed FMA.
// Double-buffered: B via cp.async, A via register staging.
__global__ __launch_bounds__(256, 2) void gemm_kernel(
    const float* __restrict__ A, const float* __restrict__ W,
    float* __restrict__ out, int K)
{
    __shared__ __align__(16) float As[2][8][128];
    __shared__ __align__(16) float Bs[2][8][128];
    int tid = threadIdx.x;
    int m0 = blockIdx.y * 128, n0 = blockIdx.x * 128;
    int arow = tid >> 1, aq = (tid & 1) * 4;
    int brow = tid >> 5, bcol = (tid & 31) * 4;
    int tx = tid & 15, ty = tid >> 4;

    unsigned long long acc[8][4];
#pragma unroll
    for (int i = 0; i < 8; i++)
#pragma unroll
        for (int j = 0; j < 4; j++) acc[i][j] = 0ULL;

    const float* aptr = &A[(size_t)(m0 + arow) * K + aq];
    const float* bptr = &W[(size_t)brow * F + n0 + bcol];

    // prologue: tile 0
    float4 av = *(const float4*)aptr;
    cp_async16(&Bs[0][brow][bcol], bptr);
    asm volatile("cp.async.commit_group;" ::: "memory");
    As[0][aq + 0][arow] = av.x; As[0][aq + 1][arow] = av.y;
    As[0][aq + 2][arow] = av.z; As[0][aq + 3][arow] = av.w;
    asm volatile("cp.async.wait_group 0;" ::: "memory");
    __syncthreads();

    int niter = K >> 3;
    int buf = 0;
    for (int it = 0; it < niter; it++) {
        float4 av2;
        if (it + 1 < niter) {
            av2 = *(const float4*)(aptr + (size_t)(it + 1) * 8);
            cp_async16(&Bs[buf ^ 1][brow][bcol], bptr + (size_t)(it + 1) * 8 * F);
            asm volatile("cp.async.commit_group;" ::: "memory");
        }
#pragma unroll
        for (int k = 0; k < 8; k++) {
            float4 a0 = *(const float4*)&As[buf][k][ty * 8];
            float4 a1 = *(const float4*)&As[buf][k][ty * 8 + 4];
            ulonglong2 b0 = *(const ulonglong2*)&Bs[buf][k][tx * 8];
            ulonglong2 b1 = *(const ulonglong2*)&Bs[buf][k][tx * 8 + 4];
            float a[8] = {a0.x, a0.y, a0.z, a0.w, a1.x, a1.y, a1.z, a1.w};
#pragma unroll
            for (int i = 0; i < 8; i++) {
                unsigned long long ap = pack2_dup(a[i]);
                acc[i][0] = ffma2(ap, b0.x, acc[i][0]);
                acc[i][1] = ffma2(ap, b0.y, acc[i][1]);
                acc[i][2] = ffma2(ap, b1.x, acc[i][2]);
                acc[i][3] = ffma2(ap, b1.y, acc[i][3]);
            }
        }
        if (it + 1 < niter) {
            As[buf ^ 1][aq + 0][arow] = av2.x; As[buf ^ 1][aq + 1][arow] = av2.y;
            As[buf ^ 1][aq + 2][arow] = av2.z; As[buf ^ 1][aq + 3][arow] = av2.w;
            asm volatile("cp.async.wait_group 0;" ::: "memory");
            __syncthreads();
        }
        buf ^= 1;
    }

#pragma unroll
    for (int i = 0; i < 8; i++) {
        int m = m0 + ty * 8 + i;
        float2 p0 = unpack2(acc[i][0]);
        float2 p1 = unpack2(acc[i][1]);
        float2 p2 = unpack2(acc[i][2]);
        float2 p3 = unpack2(acc[i][3]);
        *(float4*)&out[(size_t)m * F + n0 + tx * 8]     = make_float4(p0.x, p0.y, p1.x, p1.y);
        *(float4*)&out[(size_t)m * F + n0 + tx * 8 + 4] = make_float4(p2.x, p2.y, p3.x, p3.y);
    }
}

// ---------------- Aggregation: warp per destination node --------------------
// out[dst] = act( dis[dst] * (sum_src dis[src]*hp[src] + dis[dst]*hp[dst]) + b )
__global__ __launch_bounds__(256) void agg_kernel(
    const float* __restrict__ hp, const float* __restrict__ bias,
    float* __restrict__ out, int relu)
{
    int warp = (blockIdx.x * blockDim.x + threadIdx.x) >> 5;
    if (warp >= N_TOTAL) return;
    int lane = threadIdx.x & 31;
    const float4* hp4 = (const float4*)hp;
    int dst = warp;
    float dd = g_dis[dst];

    float4 sv0 = hp4[(size_t)dst * 64 + lane];
    float4 sv1 = hp4[(size_t)dst * 64 + 32 + lane];
    float4 acc0 = make_float4(dd * sv0.x, dd * sv0.y, dd * sv0.z, dd * sv0.w);
    float4 acc1 = make_float4(dd * sv1.x, dd * sv1.y, dd * sv1.z, dd * sv1.w);

    int e = g_rowptr[dst], end = g_rowptr[dst + 1];
    for (; e + 1 < end; e += 2) {
        int s0 = g_col[e], s1 = g_col[e + 1];
        float w0 = g_dis[s0], w1 = g_dis[s1];
        float4 v00 = hp4[(size_t)s0 * 64 + lane];
        float4 v01 = hp4[(size_t)s0 * 64 + 32 + lane];
        float4 v10 = hp4[(size_t)s1 * 64 + lane];
        float4 v11 = hp4[(size_t)s1 * 64 + 32 + lane];
        acc0.x = fmaf(w0, v00.x, fmaf(w1, v10.x, acc0.x));
        acc0.y = fmaf(w0, v00.y, fmaf(w1, v10.y, acc0.y));
        acc0.z = fmaf(w0, v00.z, fmaf(w1, v10.z, acc0.z));
        acc0.w = fmaf(w0, v00.w, fmaf(w1, v10.w, acc0.w));
        acc1.x = fmaf(w0, v01.x, fmaf(w1, v11.x, acc1.x));
        acc1.y = fmaf(w0, v01.y, fmaf(w1, v11.y, acc1.y));
        acc1.z = fmaf(w0, v01.z, fmaf(w1, v11.z, acc1.z));
        acc1.w = fmaf(w0, v01.w, fmaf(w1, v11.w, acc1.w));
    }
    if (e < end) {
        int s0 = g_col[e];
        float w0 = g_dis[s0];
        float4 v00 = hp4[(size_t)s0 * 64 + lane];
        float4 v01 = hp4[(size_t)s0 * 64 + 32 + lane];
        acc0.x = fmaf(w0, v00.x, acc0.x); acc0.y = fmaf(w0, v00.y, acc0.y);
        acc0.z = fmaf(w0, v00.z, acc0.z); acc0.w = fmaf(w0, v00.w, acc0.w);
        acc1.x = fmaf(w0, v01.x, acc1.x); acc1.y = fmaf(w0, v01.y, acc1.y);
        acc1.z = fmaf(w0, v01.z, acc1.z); acc1.w = fmaf(w0, v01.w, acc1.w);
    }

    const float4* b4 = (const float4*)bias;
    float4 b0 = b4[lane], b1 = b4[32 + lane];
    float4 r0 = make_float4(fmaf(dd, acc0.x, b0.x), fmaf(dd, acc0.y, b0.y),
                            fmaf(dd, acc0.z, b0.z), fmaf(dd, acc0.w, b0.w));
    float4 r1 = make_float4(fmaf(dd, acc1.x, b1.x), fmaf(dd, acc1.y, b1.y),
                            fmaf(dd, acc1.z, b1.z), fmaf(dd, acc1.w, b1.w));
    if (relu) {
        r0.x = fmaxf(r0.x, 0.f); r0.y = fmaxf(r0.y, 0.f);
        r0.z = fmaxf(r0.z, 0.f); r0.w = fmaxf(r0.w, 0.f);
        r1.x = fmaxf(r1.x, 0.f); r1.y = fmaxf(r1.y, 0.f);
        r1.z = fmaxf(r1.z, 0.f); r1.w = fmaxf(r1.w, 0.f);
    }
    float4* o4 = (float4*)out;
    o4[(size_t)dst * 64 + lane]      = r0;
    o4[(size_t)dst * 64 + 32 + lane] = r1;
}

// ---------------- readout (meanmax) + final linear, one CTA per graph -------
__global__ __launch_bounds__(256) void readout_kernel(
    const float* __restrict__ h, const float* __restrict__ Wm,
    const float* __restrict__ bm, float* __restrict__ out)
{
    int g = blockIdx.x;
    int t = threadIdx.x;   // 256 threads = one per feature
    const float* base = h + (size_t)g * NODES_PER_G * F;
    float s = 0.f, mx = -INFINITY;
    for (int i = 0; i < NODES_PER_G; i++) {
        float v = base[(size_t)i * F + t];
        s += v;
        mx = fmaxf(mx, v);
    }
    __shared__ float gf[2 * F];
    gf[t]     = s * (1.0f / NODES_PER_G);
    gf[F + t] = mx;
    __syncthreads();

    float p0 = gf[t] * Wm[t * 2 + 0] + gf[F + t] * Wm[(F + t) * 2 + 0];
    float p1 = gf[t] * Wm[t * 2 + 1] + gf[F + t] * Wm[(F + t) * 2 + 1];
    __shared__ float r0[256], r1[256];
    r0[t] = p0; r1[t] = p1;
    __syncthreads();
    for (int off = 128; off > 0; off >>= 1) {
        if (t < off) { r0[t] += r0[t + off]; r1[t] += r1[t + off]; }
        __syncthreads();
    }
    if (t == 0) {
        out[g * 2 + 0] = r0[0] + bm[0];
        out[g * 2 + 1] = r1[0] + bm[1];
    }
}

// ---------------- launcher --------------------------------------------------
extern "C" void kernel_launch(void* const* d_in, const int* in_sizes, int n_in,
                              void* d_out, int out_size)
{
    // Input order: x, edge_index, batch, [num_graphs], W1, b1, W2, b2, Wm, bm
    int base = (in_sizes[3] == 1) ? 4 : 3;
    const float* x  = (const float*)d_in[0];
    const void*  ei = d_in[1];
    const float* W1 = (const float*)d_in[base + 0];
    const float* b1 = (const float*)d_in[base + 1];
    const float* W2 = (const float*)d_in[base + 2];
    const float* b2 = (const float*)d_in[base + 3];
    const float* Wm = (const float*)d_in[base + 4];
    const float* bm = (const float*)d_in[base + 5];
    float* out = (float*)d_out;

    float *hp = nullptr, *buf = nullptr;
    cudaGetSymbolAddress((void**)&hp,  g_hp);
    cudaGetSymbolAddress((void**)&buf, g_buf);

    const int TB = 256;
    dim3 gg(F / 128, N_TOTAL / 128);

    init_kernel<<<(N_TOTAL + TB - 1) / TB, TB>>>();
    detect_kernel<<<1, 1024>>>((const unsigned int*)ei);
    count_kernel<<<(E_TOTAL + TB - 1) / TB, TB>>>(ei);
    // gemm1 hoisted early (no CSR dependency): hp = x @ W1
    gemm_kernel<<<gg, 256>>>(x, W1, hp, 400);
    scan_dis_kernel<<<1, 1024>>>();
    fill_kernel<<<(E_TOTAL + TB - 1) / TB, TB>>>(ei);
    // agg1: buf = relu(dis*(sum dis*hp) + b1)
    agg_kernel<<<N_TOTAL / 8, 256>>>(hp, b1, buf, 1);
    // layer 2: hp = buf @ W2
    gemm_kernel<<<gg, 256>>>(buf, W2, hp, 256);
    // agg2: buf = dis*(sum dis*hp) + b2
    agg_kernel<<<N_TOTAL / 8, 256>>>(hp, b2, buf, 0);
    // readout + final linear
    readout_kernel<<<NUM_G, 256>>>(buf, Wm, bm, out);
}

// round 4
// speedup vs baseline: 1.4190x; 1.3764x over previous
#include <cuda_runtime.h>
#include <cuda_bf16.h>
#include <math.h>

#define N_TOTAL 102400
#define E_TOTAL 4096000
#define F 256
#define NODES_PER_G 400
#define NUM_G 256

// ---------------- scratch (device globals; no allocation allowed) -----------
__device__ int   g_deg[N_TOTAL];
__device__ int   g_cursor[N_TOTAL];
__device__ int   g_rowptr[N_TOTAL + 1];
__device__ int   g_col[E_TOTAL];
__device__ float g_dis[N_TOTAL];
__device__ float g_hp[(size_t)N_TOTAL * F];   // ~105 MB
__device__ float g_buf[(size_t)N_TOTAL * F];  // ~105 MB
__device__ int   g_is64;
// pre-split, transposed weights: [N=256][K] bf16 (hi/lo)
__device__ unsigned short g_w1hi[256 * 400];
__device__ unsigned short g_w1lo[256 * 400];
__device__ unsigned short g_w2hi[256 * 256];
__device__ unsigned short g_w2lo[256 * 256];

__device__ __forceinline__ void cp_async16(void* smem_dst, const void* gmem_src) {
    unsigned long long sa = __cvta_generic_to_shared(smem_dst);
    asm volatile("cp.async.cg.shared.global [%0], [%1], 16;"
                 :: "l"(sa), "l"(gmem_src) : "memory");
}

// ---------------- setup kernels --------------------------------------------
__global__ void init_kernel() {
    int i = blockIdx.x * blockDim.x + threadIdx.x;
    if (i < N_TOTAL) { g_deg[i] = 1; g_cursor[i] = 0; }  // deg starts at 1 (self loop)
}

__global__ void detect_kernel(const unsigned int* __restrict__ w) {
    __shared__ int any;
    if (threadIdx.x == 0) any = 0;
    __syncthreads();
    int idx = 1 + 2 * (int)threadIdx.x;   // odd words 1..2047
    if (w[idx] != 0u) atomicOr(&any, 1);
    __syncthreads();
    if (threadIdx.x == 0) g_is64 = (any ? 0 : 1);
}

__device__ __forceinline__ int load_idx(const void* ei, long long pos) {
    if (g_is64) return (int)((const long long*)ei)[pos];
    return ((const int*)ei)[pos];
}

__global__ void count_kernel(const void* __restrict__ ei) {
    int e = blockIdx.x * blockDim.x + threadIdx.x;
    if (e >= E_TOTAL) return;
    int dst = load_idx(ei, (long long)E_TOTAL + e);
    atomicAdd(&g_deg[dst], 1);
}

__global__ void scan_dis_kernel() {
    __shared__ int s[1024];
    __shared__ int carry_s;
    int tid = threadIdx.x;
    if (tid == 0) carry_s = 0;
    __syncthreads();
    for (int base = 0; base < N_TOTAL; base += 1024) {
        int i = base + tid;
        int d = g_deg[i];
        g_dis[i] = rsqrtf((float)d);
        int v = d - 1;
        s[tid] = v;
        __syncthreads();
        for (int off = 1; off < 1024; off <<= 1) {
            int t = 0;
            if (tid >= off) t = s[tid - off];
            __syncthreads();
            s[tid] += t;
            __syncthreads();
        }
        int carry = carry_s;
        g_rowptr[i] = carry + s[tid] - v;   // exclusive
        int tot = s[1023];
        __syncthreads();
        if (tid == 0) carry_s = carry + tot;
        __syncthreads();
    }
    if (tid == 0) g_rowptr[N_TOTAL] = carry_s;
}

__global__ void fill_kernel(const void* __restrict__ ei) {
    int e = blockIdx.x * blockDim.x + threadIdx.x;
    if (e >= E_TOTAL) return;
    int src = load_idx(ei, e);
    int dst = load_idx(ei, (long long)E_TOTAL + e);
    int p = atomicAdd(&g_cursor[dst], 1);
    g_col[g_rowptr[dst] + p] = src;
}

// ---------------- weight split+transpose: W[K][256] -> hi/lo [256][K] -------
__global__ void wsplit_kernel(const float* __restrict__ W, int K,
                              unsigned short* __restrict__ hi,
                              unsigned short* __restrict__ lo) {
    int idx = blockIdx.x * blockDim.x + threadIdx.x;
    if (idx >= K * 256) return;
    int n = idx / K, k = idx % K;
    float a = W[(size_t)k * 256 + n];
    __nv_bfloat16 h = __float2bfloat16_rn(a);
    float hf = __bfloat162float(h);
    __nv_bfloat16 l = __float2bfloat16_rn(a - hf);
    hi[(size_t)n * K + k] = __bfloat16_as_ushort(h);
    lo[(size_t)n * K + k] = __bfloat16_as_ushort(l);
}

// ---------------- bf16x3 tensor-core GEMM: out = A @ W ----------------------
// A fp32 [M][K] split on-the-fly; W pre-split bf16 [256][K] (n-major).
// BM=128, BN=128, BK=16; 8 warps, warp tile 64x32; mma.m16n8k16, 3 passes.
#define GBK 16
#define SM_STRIDE 48            // padded row stride (bytes) for 16-bf16 rows
#define BUF_BYTES 24576         // Ahi(6144) Alo(6144) Bhi(6144) Blo(6144)
#define OFF_ALO 6144
#define OFF_BHI 12288
#define OFF_BLO 18432

__device__ __forceinline__ void bsplit2(float a0, float a1,
                                        unsigned int& hi, unsigned int& lo) {
    __nv_bfloat16 h0 = __float2bfloat16_rn(a0);
    __nv_bfloat16 h1 = __float2bfloat16_rn(a1);
    float f0 = __bfloat162float(h0), f1 = __bfloat162float(h1);
    __nv_bfloat16 l0 = __float2bfloat16_rn(a0 - f0);
    __nv_bfloat16 l1 = __float2bfloat16_rn(a1 - f1);
    hi = (unsigned int)__bfloat16_as_ushort(h0) |
         ((unsigned int)__bfloat16_as_ushort(h1) << 16);
    lo = (unsigned int)__bfloat16_as_ushort(l0) |
         ((unsigned int)__bfloat16_as_ushort(l1) << 16);
}

__device__ __forceinline__ void ldsm_x4(unsigned int addr, unsigned int* r) {
    asm volatile("ldmatrix.sync.aligned.m8n8.x4.shared.b16 {%0,%1,%2,%3}, [%4];"
                 : "=r"(r[0]), "=r"(r[1]), "=r"(r[2]), "=r"(r[3]) : "r"(addr));
}
__device__ __forceinline__ void ldsm_x2(unsigned int addr, unsigned int* r) {
    asm volatile("ldmatrix.sync.aligned.m8n8.x2.shared.b16 {%0,%1}, [%2];"
                 : "=r"(r[0]), "=r"(r[1]) : "r"(addr));
}
__device__ __forceinline__ void mma16816(float* c, const unsigned int* a,
                                         const unsigned int* b) {
    asm volatile(
        "mma.sync.aligned.m16n8k16.row.col.f32.bf16.bf16.f32 "
        "{%0,%1,%2,%3}, {%4,%5,%6,%7}, {%8,%9}, {%0,%1,%2,%3};"
        : "+f"(c[0]), "+f"(c[1]), "+f"(c[2]), "+f"(c[3])
        : "r"(a[0]), "r"(a[1]), "r"(a[2]), "r"(a[3]), "r"(b[0]), "r"(b[1]));
}

__global__ __launch_bounds__(256) void gemm_tc_kernel(
    const float* __restrict__ A,
    const unsigned short* __restrict__ Whi,
    const unsigned short* __restrict__ Wlo,
    float* __restrict__ out, int K)
{
    __shared__ __align__(16) unsigned char smem[2 * BUF_BYTES];
    unsigned int sbase = (unsigned int)__cvta_generic_to_shared(smem);
    int tid = threadIdx.x, lane = tid & 31, wid = tid >> 5;
    int wm = wid & 1, wn = wid >> 1;       // warp grid 2(M) x 4(N)
    int m0 = blockIdx.y * 128, n0 = blockIdx.x * 128;

    float acc[4][4][4];
#pragma unroll
    for (int i = 0; i < 4; i++)
#pragma unroll
        for (int j = 0; j < 4; j++)
#pragma unroll
            for (int q = 0; q < 4; q++) acc[i][j][q] = 0.f;

    // loader mappings
    int am[2], akq[2];
    {
        int id0 = tid, id1 = tid + 256;
        am[0] = id0 >> 2; akq[0] = id0 & 3;
        am[1] = id1 >> 2; akq[1] = id1 & 3;
    }
    int bn = (tid & 255) >> 1, bc = tid & 1;   // each thread: 1 hi chunk + 1 lo chunk

    const int niter = K / GBK;
    float4 stA[2];

    // ---- prologue: tile 0
#pragma unroll
    for (int t = 0; t < 2; t++)
        stA[t] = *(const float4*)&A[(size_t)(m0 + am[t]) * K + akq[t] * 4];
    {
        const unsigned short* srcH = &Whi[(size_t)(n0 + bn) * K + bc * 8];
        const unsigned short* srcL = &Wlo[(size_t)(n0 + bn) * K + bc * 8];
        cp_async16(smem + OFF_BHI + bn * SM_STRIDE + bc * 16, srcH);
        cp_async16(smem + OFF_BLO + bn * SM_STRIDE + bc * 16, srcL);
        asm volatile("cp.async.commit_group;" ::: "memory");
    }
#pragma unroll
    for (int t = 0; t < 2; t++) {
        unsigned int h01, l01, h23, l23;
        bsplit2(stA[t].x, stA[t].y, h01, l01);
        bsplit2(stA[t].z, stA[t].w, h23, l23);
        *(uint2*)(smem + am[t] * SM_STRIDE + akq[t] * 8) = make_uint2(h01, h23);
        *(uint2*)(smem + OFF_ALO + am[t] * SM_STRIDE + akq[t] * 8) = make_uint2(l01, l23);
    }
    asm volatile("cp.async.wait_group 0;" ::: "memory");
    __syncthreads();

    // fragment address components (fixed per thread)
    int aRow = wm * 64 + ((lane >> 3) & 1) * 8 + (lane & 7);
    int aKb  = (lane >> 4) * 16;
    int l4 = lane & 15;
    int bRow = wn * 32 + (l4 & 7);
    int bKb  = (l4 >> 3) * 16;

    int buf = 0;
    for (int it = 0; it < niter; it++) {
        if (it + 1 < niter) {
#pragma unroll
            for (int t = 0; t < 2; t++)
                stA[t] = *(const float4*)&A[(size_t)(m0 + am[t]) * K + (it + 1) * GBK + akq[t] * 4];
            unsigned char* nb = smem + (buf ^ 1) * BUF_BYTES;
            const unsigned short* srcH = &Whi[(size_t)(n0 + bn) * K + (it + 1) * GBK + bc * 8];
            const unsigned short* srcL = &Wlo[(size_t)(n0 + bn) * K + (it + 1) * GBK + bc * 8];
            cp_async16(nb + OFF_BHI + bn * SM_STRIDE + bc * 16, srcH);
            cp_async16(nb + OFF_BLO + bn * SM_STRIDE + bc * 16, srcL);
            asm volatile("cp.async.commit_group;" ::: "memory");
        }

        unsigned int base = sbase + buf * BUF_BYTES;
        unsigned int aHi[4][4], aLo[4][4], bHi[4][2], bLo[4][2];
#pragma unroll
        for (int mt = 0; mt < 4; mt++) {
            unsigned int ra = base + (aRow + mt * 16) * SM_STRIDE + aKb;
            ldsm_x4(ra, aHi[mt]);
            ldsm_x4(ra + OFF_ALO, aLo[mt]);
        }
#pragma unroll
        for (int nt = 0; nt < 4; nt++) {
            unsigned int rb = base + OFF_BHI + (bRow + nt * 8) * SM_STRIDE + bKb;
            ldsm_x2(rb, bHi[nt]);
            ldsm_x2(rb + (OFF_BLO - OFF_BHI), bLo[nt]);
        }
#pragma unroll
        for (int mt = 0; mt < 4; mt++)
#pragma unroll
            for (int nt = 0; nt < 4; nt++) {
                mma16816(acc[mt][nt], aHi[mt], bHi[nt]);
                mma16816(acc[mt][nt], aHi[mt], bLo[nt]);
                mma16816(acc[mt][nt], aLo[mt], bHi[nt]);
            }

        if (it + 1 < niter) {
            unsigned char* nb = smem + (buf ^ 1) * BUF_BYTES;
#pragma unroll
            for (int t = 0; t < 2; t++) {
                unsigned int h01, l01, h23, l23;
                bsplit2(stA[t].x, stA[t].y, h01, l01);
                bsplit2(stA[t].z, stA[t].w, h23, l23);
                *(uint2*)(nb + am[t] * SM_STRIDE + akq[t] * 8) = make_uint2(h01, h23);
                *(uint2*)(nb + OFF_ALO + am[t] * SM_STRIDE + akq[t] * 8) = make_uint2(l01, l23);
            }
            asm volatile("cp.async.wait_group 0;" ::: "memory");
        }
        __syncthreads();
        buf ^= 1;
    }

    // epilogue: C frag c0,c1 at (m = l/4, n = 2(l%4)); c2,c3 at m+8
    int cm = lane >> 2, cn = (lane & 3) * 2;
#pragma unroll
    for (int mt = 0; mt < 4; mt++)
#pragma unroll
        for (int nt = 0; nt < 4; nt++) {
            int row = m0 + wm * 64 + mt * 16 + cm;
            int col = n0 + wn * 32 + nt * 8 + cn;
            *(float2*)&out[(size_t)row * F + col] =
                make_float2(acc[mt][nt][0], acc[mt][nt][1]);
            *(float2*)&out[(size_t)(row + 8) * F + col] =
                make_float2(acc[mt][nt][2], acc[mt][nt][3]);
        }
}

// ---------------- Aggregation: warp per destination node --------------------
__global__ __launch_bounds__(256) void agg_kernel(
    const float* __restrict__ hp, const float* __restrict__ bias,
    float* __restrict__ out, int relu)
{
    int warp = (blockIdx.x * blockDim.x + threadIdx.x) >> 5;
    if (warp >= N_TOTAL) return;
    int lane = threadIdx.x & 31;
    const float4* hp4 = (const float4*)hp;
    int dst = warp;
    float dd = g_dis[dst];

    float4 sv0 = hp4[(size_t)dst * 64 + lane];
    float4 sv1 = hp4[(size_t)dst * 64 + 32 + lane];
    float4 acc0 = make_float4(dd * sv0.x, dd * sv0.y, dd * sv0.z, dd * sv0.w);
    float4 acc1 = make_float4(dd * sv1.x, dd * sv1.y, dd * sv1.z, dd * sv1.w);

    int e = g_rowptr[dst], end = g_rowptr[dst + 1];
    for (; e + 1 < end; e += 2) {
        int s0 = g_col[e], s1 = g_col[e + 1];
        float w0 = g_dis[s0], w1 = g_dis[s1];
        float4 v00 = hp4[(size_t)s0 * 64 + lane];
        float4 v01 = hp4[(size_t)s0 * 64 + 32 + lane];
        float4 v10 = hp4[(size_t)s1 * 64 + lane];
        float4 v11 = hp4[(size_t)s1 * 64 + 32 + lane];
        acc0.x = fmaf(w0, v00.x, fmaf(w1, v10.x, acc0.x));
        acc0.y = fmaf(w0, v00.y, fmaf(w1, v10.y, acc0.y));
        acc0.z = fmaf(w0, v00.z, fmaf(w1, v10.z, acc0.z));
        acc0.w = fmaf(w0, v00.w, fmaf(w1, v10.w, acc0.w));
        acc1.x = fmaf(w0, v01.x, fmaf(w1, v11.x, acc1.x));
        acc1.y = fmaf(w0, v01.y, fmaf(w1, v11.y, acc1.y));
        acc1.z = fmaf(w0, v01.z, fmaf(w1, v11.z, acc1.z));
        acc1.w = fmaf(w0, v01.w, fmaf(w1, v11.w, acc1.w));
    }
    if (e < end) {
        int s0 = g_col[e];
        float w0 = g_dis[s0];
        float4 v00 = hp4[(size_t)s0 * 64 + lane];
        float4 v01 = hp4[(size_t)s0 * 64 + 32 + lane];
        acc0.x = fmaf(w0, v00.x, acc0.x); acc0.y = fmaf(w0, v00.y, acc0.y);
        acc0.z = fmaf(w0, v00.z, acc0.z); acc0.w = fmaf(w0, v00.w, acc0.w);
        acc1.x = fmaf(w0, v01.x, acc1.x); acc1.y = fmaf(w0, v01.y, acc1.y);
        acc1.z = fmaf(w0, v01.z, acc1.z); acc1.w = fmaf(w0, v01.w, acc1.w);
    }

    const float4* b4 = (const float4*)bias;
    float4 b0 = b4[lane], b1 = b4[32 + lane];
    float4 r0 = make_float4(fmaf(dd, acc0.x, b0.x), fmaf(dd, acc0.y, b0.y),
                            fmaf(dd, acc0.z, b0.z), fmaf(dd, acc0.w, b0.w));
    float4 r1 = make_float4(fmaf(dd, acc1.x, b1.x), fmaf(dd, acc1.y, b1.y),
                            fmaf(dd, acc1.z, b1.z), fmaf(dd, acc1.w, b1.w));
    if (relu) {
        r0.x = fmaxf(r0.x, 0.f); r0.y = fmaxf(r0.y, 0.f);
        r0.z = fmaxf(r0.z, 0.f); r0.w = fmaxf(r0.w, 0.f);
        r1.x = fmaxf(r1.x, 0.f); r1.y = fmaxf(r1.y, 0.f);
        r1.z = fmaxf(r1.z, 0.f); r1.w = fmaxf(r1.w, 0.f);
    }
    float4* o4 = (float4*)out;
    o4[(size_t)dst * 64 + lane]      = r0;
    o4[(size_t)dst * 64 + 32 + lane] = r1;
}

// ---------------- readout (meanmax) + final linear, one CTA per graph -------
__global__ __launch_bounds__(256) void readout_kernel(
    const float* __restrict__ h, const float* __restrict__ Wm,
    const float* __restrict__ bm, float* __restrict__ out)
{
    int g = blockIdx.x;
    int t = threadIdx.x;
    const float* base = h + (size_t)g * NODES_PER_G * F;
    float s = 0.f, mx = -INFINITY;
    for (int i = 0; i < NODES_PER_G; i++) {
        float v = base[(size_t)i * F + t];
        s += v;
        mx = fmaxf(mx, v);
    }
    __shared__ float gf[2 * F];
    gf[t]     = s * (1.0f / NODES_PER_G);
    gf[F + t] = mx;
    __syncthreads();

    float p0 = gf[t] * Wm[t * 2 + 0] + gf[F + t] * Wm[(F + t) * 2 + 0];
    float p1 = gf[t] * Wm[t * 2 + 1] + gf[F + t] * Wm[(F + t) * 2 + 1];
    __shared__ float r0[256], r1[256];
    r0[t] = p0; r1[t] = p1;
    __syncthreads();
    for (int off = 128; off > 0; off >>= 1) {
        if (t < off) { r0[t] += r0[t + off]; r1[t] += r1[t + off]; }
        __syncthreads();
    }
    if (t == 0) {
        out[g * 2 + 0] = r0[0] + bm[0];
        out[g * 2 + 1] = r1[0] + bm[1];
    }
}

// ---------------- launcher --------------------------------------------------
extern "C" void kernel_launch(void* const* d_in, const int* in_sizes, int n_in,
                              void* d_out, int out_size)
{
    int base = (in_sizes[3] == 1) ? 4 : 3;
    const float* x  = (const float*)d_in[0];
    const void*  ei = d_in[1];
    const float* W1 = (const float*)d_in[base + 0];
    const float* b1 = (const float*)d_in[base + 1];
    const float* W2 = (const float*)d_in[base + 2];
    const float* b2 = (const float*)d_in[base + 3];
    const float* Wm = (const float*)d_in[base + 4];
    const float* bm = (const float*)d_in[base + 5];
    float* out = (float*)d_out;

    float *hp = nullptr, *buf = nullptr;
    unsigned short *w1hi, *w1lo, *w2hi, *w2lo;
    cudaGetSymbolAddress((void**)&hp,  g_hp);
    cudaGetSymbolAddress((void**)&buf, g_buf);
    cudaGetSymbolAddress((void**)&w1hi, g_w1hi);
    cudaGetSymbolAddress((void**)&w1lo, g_w1lo);
    cudaGetSymbolAddress((void**)&w2hi, g_w2hi);
    cudaGetSymbolAddress((void**)&w2lo, g_w2lo);

    const int TB = 256;
    dim3 gg(2, N_TOTAL / 128);   // (N tiles, M tiles)

    init_kernel<<<(N_TOTAL + TB - 1) / TB, TB>>>();
    detect_kernel<<<1, 1024>>>((const unsigned int*)ei);
    count_kernel<<<(E_TOTAL + TB - 1) / TB, TB>>>(ei);
    wsplit_kernel<<<(400 * 256 + TB - 1) / TB, TB>>>(W1, 400, w1hi, w1lo);
    wsplit_kernel<<<(256 * 256 + TB - 1) / TB, TB>>>(W2, 256, w2hi, w2lo);
    // gemm1: hp = x @ W1 (bf16x3 tensor cores)
    gemm_tc_kernel<<<gg, 256>>>(x, w1hi, w1lo, hp, 400);
    scan_dis_kernel<<<1, 1024>>>();
    fill_kernel<<<(E_TOTAL + TB - 1) / TB, TB>>>(ei);
    // agg1: buf = relu(dis*(sum dis*hp) + b1)
    agg_kernel<<<N_TOTAL / 8, 256>>>(hp, b1, buf, 1);
    // gemm2: hp = buf @ W2
    gemm_tc_kernel<<<gg, 256>>>(buf, w2hi, w2lo, hp, 256);
    // agg2: buf = dis*(sum dis*hp) + b2
    agg_kernel<<<N_TOTAL / 8, 256>>>(hp, b2, buf, 0);
    readout_kernel<<<NUM_G, 256>>>(buf, Wm, bm, out);
}

// round 5
// speedup vs baseline: 2.2285x; 1.5705x over previous
#include <cuda_runtime.h>
#include <cuda_bf16.h>
#include <cuda_fp16.h>
#include <math.h>

#define N_TOTAL 102400
#define E_TOTAL 4096000
#define F 256
#define NODES_PER_G 400
#define NUM_G 256

// ---------------- scratch (device globals; no allocation allowed) -----------
__device__ int   g_deg[N_TOTAL];
__device__ int   g_cursor[N_TOTAL];
__device__ int   g_rowptr[N_TOTAL + 1];
__device__ int   g_boff[401];
__device__ int   g_col[E_TOTAL];
__device__ float g_dis[N_TOTAL];
__device__ __half g_hps[(size_t)N_TOTAL * F];  // ~52 MB, L2-resident
__device__ float  g_buf[(size_t)N_TOTAL * F];  // ~105 MB
__device__ int   g_is64;
// pre-split, transposed weights: [N=256][K] bf16 (hi/lo)
__device__ unsigned short g_w1hi[256 * 400];
__device__ unsigned short g_w1lo[256 * 400];
__device__ unsigned short g_w2hi[256 * 256];
__device__ unsigned short g_w2lo[256 * 256];

__device__ __forceinline__ void cp_async16(void* smem_dst, const void* gmem_src) {
    unsigned long long sa = __cvta_generic_to_shared(smem_dst);
    asm volatile("cp.async.cg.shared.global [%0], [%1], 16;"
                 :: "l"(sa), "l"(gmem_src) : "memory");
}

// ---------------- setup kernels --------------------------------------------
__global__ void init_kernel() {
    int i = blockIdx.x * blockDim.x + threadIdx.x;
    if (i < N_TOTAL) { g_deg[i] = 0; g_cursor[i] = 0; }
}

__global__ void detect_kernel(const unsigned int* __restrict__ w) {
    __shared__ int any;
    if (threadIdx.x == 0) any = 0;
    __syncthreads();
    int idx = 1 + 2 * (int)threadIdx.x;   // odd words 1..2047
    if (w[idx] != 0u) atomicOr(&any, 1);
    __syncthreads();
    if (threadIdx.x == 0) g_is64 = (any ? 0 : 1);
}

__device__ __forceinline__ int load_idx(const void* ei, long long pos) {
    if (g_is64) return (int)((const long long*)ei)[pos];
    return ((const int*)ei)[pos];
}

// two edges per thread, vectorized dst load
__global__ void count_kernel(const void* __restrict__ ei) {
    int t = blockIdx.x * blockDim.x + threadIdx.x;
    if (t * 2 >= E_TOTAL) return;
    if (g_is64) {
        longlong2 d = ((const longlong2*)((const long long*)ei + E_TOTAL))[t];
        atomicAdd(&g_deg[(int)d.x], 1);
        atomicAdd(&g_deg[(int)d.y], 1);
    } else {
        int2 d = ((const int2*)((const int*)ei + E_TOTAL))[t];
        atomicAdd(&g_deg[d.x], 1);
        atomicAdd(&g_deg[d.y], 1);
    }
}

// ---- 3-phase scan of g_deg -> g_rowptr (exclusive), plus dis = rsqrt(deg+1)
__global__ void scan1_kernel() {
    __shared__ int s[256];
    int b = blockIdx.x, tid = threadIdx.x;
    int i = b * 256 + tid;
    int d = g_deg[i];
    g_dis[i] = rsqrtf((float)(d + 1));
    s[tid] = d;
    __syncthreads();
#pragma unroll
    for (int off = 1; off < 256; off <<= 1) {
        int t = 0;
        if (tid >= off) t = s[tid - off];
        __syncthreads();
        s[tid] += t;
        __syncthreads();
    }
    g_rowptr[i] = s[tid] - d;                 // local exclusive
    if (tid == 255) g_boff[b] = s[255];       // block total (temp)
}

__global__ void scan2_kernel() {
    __shared__ int s[512];
    int tid = threadIdx.x;
    int v = (tid < 400) ? g_boff[tid] : 0;
    s[tid] = v;
    __syncthreads();
#pragma unroll
    for (int off = 1; off < 512; off <<= 1) {
        int t = 0;
        if (tid >= off) t = s[tid - off];
        __syncthreads();
        s[tid] += t;
        __syncthreads();
    }
    if (tid <= 400) g_boff[tid] = s[tid] - v; // exclusive (at 400: total)
}

__global__ void scan3_kernel() {
    int b = blockIdx.x, tid = threadIdx.x;
    int i = b * 256 + tid;
    g_rowptr[i] += g_boff[b];
    if (i == N_TOTAL - 1) g_rowptr[N_TOTAL] = g_boff[400];
}

__global__ void fill_kernel(const void* __restrict__ ei) {
    int e = blockIdx.x * blockDim.x + threadIdx.x;
    if (e >= E_TOTAL) return;
    int src = load_idx(ei, e);
    int dst = load_idx(ei, (long long)E_TOTAL + e);
    int p = atomicAdd(&g_cursor[dst], 1);
    g_col[g_rowptr[dst] + p] = src;
}

// ---------------- weight split+transpose: W[K][256] -> hi/lo [256][K] -------
__global__ void wsplit_kernel(const float* __restrict__ W, int K,
                              unsigned short* __restrict__ hi,
                              unsigned short* __restrict__ lo) {
    int idx = blockIdx.x * blockDim.x + threadIdx.x;
    if (idx >= K * 256) return;
    int n = idx / K, k = idx % K;
    float a = W[(size_t)k * 256 + n];
    __nv_bfloat16 h = __float2bfloat16_rn(a);
    float hf = __bfloat162float(h);
    __nv_bfloat16 l = __float2bfloat16_rn(a - hf);
    hi[(size_t)n * K + k] = __bfloat16_as_ushort(h);
    lo[(size_t)n * K + k] = __bfloat16_as_ushort(l);
}

// ---------------- bf16x3 tensor-core GEMM: out = fp16(dis[m] * (A @ W)) -----
#define GBK 16
#define SM_STRIDE 48
#define BUF_BYTES 24576
#define OFF_ALO 6144
#define OFF_BHI 12288
#define OFF_BLO 18432

__device__ __forceinline__ void bsplit2(float a0, float a1,
                                        unsigned int& hi, unsigned int& lo) {
    __nv_bfloat16 h0 = __float2bfloat16_rn(a0);
    __nv_bfloat16 h1 = __float2bfloat16_rn(a1);
    float f0 = __bfloat162float(h0), f1 = __bfloat162float(h1);
    __nv_bfloat16 l0 = __float2bfloat16_rn(a0 - f0);
    __nv_bfloat16 l1 = __float2bfloat16_rn(a1 - f1);
    hi = (unsigned int)__bfloat16_as_ushort(h0) |
         ((unsigned int)__bfloat16_as_ushort(h1) << 16);
    lo = (unsigned int)__bfloat16_as_ushort(l0) |
         ((unsigned int)__bfloat16_as_ushort(l1) << 16);
}

__device__ __forceinline__ void ldsm_x4(unsigned int addr, unsigned int* r) {
    asm volatile("ldmatrix.sync.aligned.m8n8.x4.shared.b16 {%0,%1,%2,%3}, [%4];"
                 : "=r"(r[0]), "=r"(r[1]), "=r"(r[2]), "=r"(r[3]) : "r"(addr));
}
__device__ __forceinline__ void ldsm_x2(unsigned int addr, unsigned int* r) {
    asm volatile("ldmatrix.sync.aligned.m8n8.x2.shared.b16 {%0,%1}, [%2];"
                 : "=r"(r[0]), "=r"(r[1]) : "r"(addr));
}
__device__ __forceinline__ void mma16816(float* c, const unsigned int* a,
                                         const unsigned int* b) {
    asm volatile(
        "mma.sync.aligned.m16n8k16.row.col.f32.bf16.bf16.f32 "
        "{%0,%1,%2,%3}, {%4,%5,%6,%7}, {%8,%9}, {%0,%1,%2,%3};"
        : "+f"(c[0]), "+f"(c[1]), "+f"(c[2]), "+f"(c[3])
        : "r"(a[0]), "r"(a[1]), "r"(a[2]), "r"(a[3]), "r"(b[0]), "r"(b[1]));
}

__global__ __launch_bounds__(256) void gemm_tc_kernel(
    const float* __restrict__ A,
    const unsigned short* __restrict__ Whi,
    const unsigned short* __restrict__ Wlo,
    __half* __restrict__ out, int K)
{
    __shared__ __align__(16) unsigned char smem[2 * BUF_BYTES];
    unsigned int sbase = (unsigned int)__cvta_generic_to_shared(smem);
    int tid = threadIdx.x, lane = tid & 31, wid = tid >> 5;
    int wm = wid & 1, wn = wid >> 1;       // warp grid 2(M) x 4(N)
    int m0 = blockIdx.y * 128, n0 = blockIdx.x * 128;

    float acc[4][4][4];
#pragma unroll
    for (int i = 0; i < 4; i++)
#pragma unroll
        for (int j = 0; j < 4; j++)
#pragma unroll
            for (int q = 0; q < 4; q++) acc[i][j][q] = 0.f;

    int am[2], akq[2];
    {
        int id0 = tid, id1 = tid + 256;
        am[0] = id0 >> 2; akq[0] = id0 & 3;
        am[1] = id1 >> 2; akq[1] = id1 & 3;
    }
    int bn = (tid & 255) >> 1, bc = tid & 1;

    const int niter = K / GBK;
    float4 stA[2];

    // ---- prologue: tile 0
#pragma unroll
    for (int t = 0; t < 2; t++)
        stA[t] = *(const float4*)&A[(size_t)(m0 + am[t]) * K + akq[t] * 4];
    {
        const unsigned short* srcH = &Whi[(size_t)(n0 + bn) * K + bc * 8];
        const unsigned short* srcL = &Wlo[(size_t)(n0 + bn) * K + bc * 8];
        cp_async16(smem + OFF_BHI + bn * SM_STRIDE + bc * 16, srcH);
        cp_async16(smem + OFF_BLO + bn * SM_STRIDE + bc * 16, srcL);
        asm volatile("cp.async.commit_group;" ::: "memory");
    }
#pragma unroll
    for (int t = 0; t < 2; t++) {
        unsigned int h01, l01, h23, l23;
        bsplit2(stA[t].x, stA[t].y, h01, l01);
        bsplit2(stA[t].z, stA[t].w, h23, l23);
        *(uint2*)(smem + am[t] * SM_STRIDE + akq[t] * 8) = make_uint2(h01, h23);
        *(uint2*)(smem + OFF_ALO + am[t] * SM_STRIDE + akq[t] * 8) = make_uint2(l01, l23);
    }
    asm volatile("cp.async.wait_group 0;" ::: "memory");
    __syncthreads();

    int aRow = wm * 64 + ((lane >> 3) & 1) * 8 + (lane & 7);
    int aKb  = (lane >> 4) * 16;
    int l4 = lane & 15;
    int bRow = wn * 32 + (l4 & 7);
    int bKb  = (l4 >> 3) * 16;

    int buf = 0;
    for (int it = 0; it < niter; it++) {
        if (it + 1 < niter) {
#pragma unroll
            for (int t = 0; t < 2; t++)
                stA[t] = *(const float4*)&A[(size_t)(m0 + am[t]) * K + (it + 1) * GBK + akq[t] * 4];
            unsigned char* nb = smem + (buf ^ 1) * BUF_BYTES;
            const unsigned short* srcH = &Whi[(size_t)(n0 + bn) * K + (it + 1) * GBK + bc * 8];
            const unsigned short* srcL = &Wlo[(size_t)(n0 + bn) * K + (it + 1) * GBK + bc * 8];
            cp_async16(nb + OFF_BHI + bn * SM_STRIDE + bc * 16, srcH);
            cp_async16(nb + OFF_BLO + bn * SM_STRIDE + bc * 16, srcL);
            asm volatile("cp.async.commit_group;" ::: "memory");
        }

        unsigned int base = sbase + buf * BUF_BYTES;
        unsigned int aHi[4][4], aLo[4][4], bHi[4][2], bLo[4][2];
#pragma unroll
        for (int mt = 0; mt < 4; mt++) {
            unsigned int ra = base + (aRow + mt * 16) * SM_STRIDE + aKb;
            ldsm_x4(ra, aHi[mt]);
            ldsm_x4(ra + OFF_ALO, aLo[mt]);
        }
#pragma unroll
        for (int nt = 0; nt < 4; nt++) {
            unsigned int rb = base + OFF_BHI + (bRow + nt * 8) * SM_STRIDE + bKb;
            ldsm_x2(rb, bHi[nt]);
            ldsm_x2(rb + (OFF_BLO - OFF_BHI), bLo[nt]);
        }
#pragma unroll
        for (int mt = 0; mt < 4; mt++)
#pragma unroll
            for (int nt = 0; nt < 4; nt++) {
                mma16816(acc[mt][nt], aHi[mt], bHi[nt]);
                mma16816(acc[mt][nt], aHi[mt], bLo[nt]);
                mma16816(acc[mt][nt], aLo[mt], bHi[nt]);
            }

        if (it + 1 < niter) {
            unsigned char* nb = smem + (buf ^ 1) * BUF_BYTES;
#pragma unroll
            for (int t = 0; t < 2; t++) {
                unsigned int h01, l01, h23, l23;
                bsplit2(stA[t].x, stA[t].y, h01, l01);
                bsplit2(stA[t].z, stA[t].w, h23, l23);
                *(uint2*)(nb + am[t] * SM_STRIDE + akq[t] * 8) = make_uint2(h01, h23);
                *(uint2*)(nb + OFF_ALO + am[t] * SM_STRIDE + akq[t] * 8) = make_uint2(l01, l23);
            }
            asm volatile("cp.async.wait_group 0;" ::: "memory");
        }
        __syncthreads();
        buf ^= 1;
    }

    // epilogue: scale by dis[row], convert to fp16, store
    int cm = lane >> 2, cn = (lane & 3) * 2;
#pragma unroll
    for (int mt = 0; mt < 4; mt++) {
        int row = m0 + wm * 64 + mt * 16 + cm;
        float d1 = g_dis[row], d2 = g_dis[row + 8];
#pragma unroll
        for (int nt = 0; nt < 4; nt++) {
            int col = n0 + wn * 32 + nt * 8 + cn;
            __half2 h01 = __floats2half2_rn(d1 * acc[mt][nt][0], d1 * acc[mt][nt][1]);
            __half2 h23 = __floats2half2_rn(d2 * acc[mt][nt][2], d2 * acc[mt][nt][3]);
            *(__half2*)&out[(size_t)row * F + col]       = h01;
            *(__half2*)&out[(size_t)(row + 8) * F + col] = h23;
        }
    }
}

// ---------------- Aggregation: warp per destination node --------------------
// out[dst] = act( dis[dst] * (sum_{src} hps[src] + hps[dst]) + b )   (hps fp16)
__device__ __forceinline__ void acc8(float* a, uint4 v) {
    float2 f0 = __half22float2(*(__half2*)&v.x);
    float2 f1 = __half22float2(*(__half2*)&v.y);
    float2 f2 = __half22float2(*(__half2*)&v.z);
    float2 f3 = __half22float2(*(__half2*)&v.w);
    a[0] += f0.x; a[1] += f0.y; a[2] += f1.x; a[3] += f1.y;
    a[4] += f2.x; a[5] += f2.y; a[6] += f3.x; a[7] += f3.y;
}

__global__ __launch_bounds__(256) void agg_kernel(
    const __half* __restrict__ hp, const float* __restrict__ bias,
    float* __restrict__ out, int relu)
{
    int warp = (blockIdx.x * blockDim.x + threadIdx.x) >> 5;
    if (warp >= N_TOTAL) return;
    int lane = threadIdx.x & 31;
    const uint4* hp4 = (const uint4*)hp;   // 8 halves per uint4; 32 per row
    int dst = warp;

    float a[8];
    {
        uint4 v = hp4[(size_t)dst * 32 + lane];
        float2 f0 = __half22float2(*(__half2*)&v.x);
        float2 f1 = __half22float2(*(__half2*)&v.y);
        float2 f2 = __half22float2(*(__half2*)&v.z);
        float2 f3 = __half22float2(*(__half2*)&v.w);
        a[0] = f0.x; a[1] = f0.y; a[2] = f1.x; a[3] = f1.y;
        a[4] = f2.x; a[5] = f2.y; a[6] = f3.x; a[7] = f3.y;
    }

    int e = g_rowptr[dst], end = g_rowptr[dst + 1];
    for (; e + 4 <= end; e += 4) {
        int s0 = g_col[e], s1 = g_col[e + 1], s2 = g_col[e + 2], s3 = g_col[e + 3];
        uint4 v0 = hp4[(size_t)s0 * 32 + lane];
        uint4 v1 = hp4[(size_t)s1 * 32 + lane];
        uint4 v2 = hp4[(size_t)s2 * 32 + lane];
        uint4 v3 = hp4[(size_t)s3 * 32 + lane];
        acc8(a, v0); acc8(a, v1); acc8(a, v2); acc8(a, v3);
    }
    for (; e < end; e++) {
        uint4 v0 = hp4[(size_t)g_col[e] * 32 + lane];
        acc8(a, v0);
    }

    float dd = g_dis[dst];
    const float4* b4 = (const float4*)bias;
    float4 b0 = b4[lane * 2], b1 = b4[lane * 2 + 1];
    float r[8];
    r[0] = fmaf(dd, a[0], b0.x); r[1] = fmaf(dd, a[1], b0.y);
    r[2] = fmaf(dd, a[2], b0.z); r[3] = fmaf(dd, a[3], b0.w);
    r[4] = fmaf(dd, a[4], b1.x); r[5] = fmaf(dd, a[5], b1.y);
    r[6] = fmaf(dd, a[6], b1.z); r[7] = fmaf(dd, a[7], b1.w);
    if (relu) {
#pragma unroll
        for (int j = 0; j < 8; j++) r[j] = fmaxf(r[j], 0.f);
    }
    float4* o4 = (float4*)&out[(size_t)dst * F + lane * 8];
    o4[0] = make_float4(r[0], r[1], r[2], r[3]);
    o4[1] = make_float4(r[4], r[5], r[6], r[7]);
}

// ---------------- readout (meanmax) + final linear, one CTA per graph -------
__global__ __launch_bounds__(256) void readout_kernel(
    const float* __restrict__ h, const float* __restrict__ Wm,
    const float* __restrict__ bm, float* __restrict__ out)
{
    int g = blockIdx.x;
    int t = threadIdx.x;
    const float* base = h + (size_t)g * NODES_PER_G * F;
    float s = 0.f, mx = -INFINITY;
    for (int i = 0; i < NODES_PER_G; i++) {
        float v = base[(size_t)i * F + t];
        s += v;
        mx = fmaxf(mx, v);
    }
    __shared__ float gf[2 * F];
    gf[t]     = s * (1.0f / NODES_PER_G);
    gf[F + t] = mx;
    __syncthreads();

    float p0 = gf[t] * Wm[t * 2 + 0] + gf[F + t] * Wm[(F + t) * 2 + 0];
    float p1 = gf[t] * Wm[t * 2 + 1] + gf[F + t] * Wm[(F + t) * 2 + 1];
    __shared__ float r0[256], r1[256];
    r0[t] = p0; r1[t] = p1;
    __syncthreads();
    for (int off = 128; off > 0; off >>= 1) {
        if (t < off) { r0[t] += r0[t + off]; r1[t] += r1[t + off]; }
        __syncthreads();
    }
    if (t == 0) {
        out[g * 2 + 0] = r0[0] + bm[0];
        out[g * 2 + 1] = r1[0] + bm[1];
    }
}

// ---------------- launcher --------------------------------------------------
extern "C" void kernel_launch(void* const* d_in, const int* in_sizes, int n_in,
                              void* d_out, int out_size)
{
    int base = (in_sizes[3] == 1) ? 4 : 3;
    const float* x  = (const float*)d_in[0];
    const void*  ei = d_in[1];
    const float* W1 = (const float*)d_in[base + 0];
    const float* b1 = (const float*)d_in[base + 1];
    const float* W2 = (const float*)d_in[base + 2];
    const float* b2 = (const float*)d_in[base + 3];
    const float* Wm = (const float*)d_in[base + 4];
    const float* bm = (const float*)d_in[base + 5];
    float* out = (float*)d_out;

    __half* hps = nullptr; float* buf = nullptr;
    unsigned short *w1hi, *w1lo, *w2hi, *w2lo;
    cudaGetSymbolAddress((void**)&hps, g_hps);
    cudaGetSymbolAddress((void**)&buf, g_buf);
    cudaGetSymbolAddress((void**)&w1hi, g_w1hi);
    cudaGetSymbolAddress((void**)&w1lo, g_w1lo);
    cudaGetSymbolAddress((void**)&w2hi, g_w2hi);
    cudaGetSymbolAddress((void**)&w2lo, g_w2lo);

    const int TB = 256;
    dim3 gg(2, N_TOTAL / 128);   // (N tiles, M tiles)

    init_kernel<<<N_TOTAL / TB, TB>>>();
    detect_kernel<<<1, 1024>>>((const unsigned int*)ei);
    count_kernel<<<(E_TOTAL / 2 + TB - 1) / TB, TB>>>(ei);
    scan1_kernel<<<400, 256>>>();
    scan2_kernel<<<1, 512>>>();
    scan3_kernel<<<400, 256>>>();
    fill_kernel<<<(E_TOTAL + TB - 1) / TB, TB>>>(ei);
    wsplit_kernel<<<(400 * 256 + TB - 1) / TB, TB>>>(W1, 400, w1hi, w1lo);
    wsplit_kernel<<<(256 * 256 + TB - 1) / TB, TB>>>(W2, 256, w2hi, w2lo);
    // gemm1: hps = fp16(dis * (x @ W1))
    gemm_tc_kernel<<<gg, 256>>>(x, w1hi, w1lo, hps, 400);
    // agg1: buf = relu(dis*(sum hps) + b1)
    agg_kernel<<<N_TOTAL / 8, 256>>>(hps, b1, buf, 1);
    // gemm2: hps = fp16(dis * (buf @ W2))
    gemm_tc_kernel<<<gg, 256>>>(buf, w2hi, w2lo, hps, 256);
    // agg2: buf = dis*(sum hps) + b2
    agg_kernel<<<N_TOTAL / 8, 256>>>(hps, b2, buf, 0);
    readout_kernel<<<NUM_G, 256>>>(buf, Wm, bm, out);
}

// round 6
// speedup vs baseline: 2.2650x; 1.0164x over previous
#include <cuda_runtime.h>
#include <cuda_bf16.h>
#include <cuda_fp16.h>
#include <math.h>

#define N_TOTAL 102400
#define E_TOTAL 4096000
#define F 256
#define NODES_PER_G 400
#define NUM_G 256

// ---------------- scratch (device globals; no allocation allowed) -----------
__device__ int   g_deg[N_TOTAL];
__device__ int   g_cursor[N_TOTAL];
__device__ int   g_rowptr[N_TOTAL + 1];
__device__ int   g_boff[401];
__device__ int   g_col[E_TOTAL];
__device__ float g_dis[N_TOTAL];
__device__ __half g_hps[(size_t)N_TOTAL * F];  // ~52 MB  (gemm out, agg in)
__device__ __half g_p16[(size_t)N_TOTAL * F];  // ~52 MB  (agg out, gemm2/readout in)
__device__ int   g_is64;
// pre-split, transposed weights: [N=256][K] bf16 (hi/lo)
__device__ unsigned short g_w1hi[256 * 400];
__device__ unsigned short g_w1lo[256 * 400];
__device__ unsigned short g_w2hi[256 * 256];
__device__ unsigned short g_w2lo[256 * 256];

__device__ __forceinline__ void cp_async16(void* smem_dst, const void* gmem_src) {
    unsigned long long sa = __cvta_generic_to_shared(smem_dst);
    asm volatile("cp.async.cg.shared.global [%0], [%1], 16;"
                 :: "l"(sa), "l"(gmem_src) : "memory");
}

// ---------------- setup kernels --------------------------------------------
__global__ void init_kernel() {
    int i = blockIdx.x * blockDim.x + threadIdx.x;
    if (i < N_TOTAL) { g_deg[i] = 0; g_cursor[i] = 0; }
}

__global__ void detect_kernel(const unsigned int* __restrict__ w) {
    __shared__ int any;
    if (threadIdx.x == 0) any = 0;
    __syncthreads();
    int idx = 1 + 2 * (int)threadIdx.x;   // odd words 1..2047
    if (w[idx] != 0u) atomicOr(&any, 1);
    __syncthreads();
    if (threadIdx.x == 0) g_is64 = (any ? 0 : 1);
}

// two edges per thread, vectorized dst load
__global__ void count_kernel(const void* __restrict__ ei) {
    int t = blockIdx.x * blockDim.x + threadIdx.x;
    if (t * 2 >= E_TOTAL) return;
    if (g_is64) {
        longlong2 d = ((const longlong2*)((const long long*)ei + E_TOTAL))[t];
        atomicAdd(&g_deg[(int)d.x], 1);
        atomicAdd(&g_deg[(int)d.y], 1);
    } else {
        int2 d = ((const int2*)((const int*)ei + E_TOTAL))[t];
        atomicAdd(&g_deg[d.x], 1);
        atomicAdd(&g_deg[d.y], 1);
    }
}

// ---- 3-phase scan of g_deg -> g_rowptr (exclusive), plus dis = rsqrt(deg+1)
__global__ void scan1_kernel() {
    __shared__ int s[256];
    int b = blockIdx.x, tid = threadIdx.x;
    int i = b * 256 + tid;
    int d = g_deg[i];
    g_dis[i] = rsqrtf((float)(d + 1));
    s[tid] = d;
    __syncthreads();
#pragma unroll
    for (int off = 1; off < 256; off <<= 1) {
        int t = 0;
        if (tid >= off) t = s[tid - off];
        __syncthreads();
        s[tid] += t;
        __syncthreads();
    }
    g_rowptr[i] = s[tid] - d;                 // local exclusive
    if (tid == 255) g_boff[b] = s[255];       // block total (temp)
}

__global__ void scan2_kernel() {
    __shared__ int s[512];
    int tid = threadIdx.x;
    int v = (tid < 400) ? g_boff[tid] : 0;
    s[tid] = v;
    __syncthreads();
#pragma unroll
    for (int off = 1; off < 512; off <<= 1) {
        int t = 0;
        if (tid >= off) t = s[tid - off];
        __syncthreads();
        s[tid] += t;
        __syncthreads();
    }
    if (tid <= 400) g_boff[tid] = s[tid] - v; // exclusive (at 400: total)
}

__global__ void scan3_kernel() {
    int b = blockIdx.x, tid = threadIdx.x;
    int i = b * 256 + tid;
    g_rowptr[i] += g_boff[b];
    if (i == N_TOTAL - 1) g_rowptr[N_TOTAL] = g_boff[400];
}

// two edges per thread
__global__ void fill_kernel(const void* __restrict__ ei) {
    int t = blockIdx.x * blockDim.x + threadIdx.x;
    if (t * 2 >= E_TOTAL) return;
    int s0, s1, d0, d1;
    if (g_is64) {
        longlong2 s = ((const longlong2*)ei)[t];
        longlong2 d = ((const longlong2*)((const long long*)ei + E_TOTAL))[t];
        s0 = (int)s.x; s1 = (int)s.y; d0 = (int)d.x; d1 = (int)d.y;
    } else {
        int2 s = ((const int2*)ei)[t];
        int2 d = ((const int2*)((const int*)ei + E_TOTAL))[t];
        s0 = s.x; s1 = s.y; d0 = d.x; d1 = d.y;
    }
    int p0 = atomicAdd(&g_cursor[d0], 1);
    g_col[g_rowptr[d0] + p0] = s0;
    int p1 = atomicAdd(&g_cursor[d1], 1);
    g_col[g_rowptr[d1] + p1] = s1;
}

// ---------------- weight split+transpose: W[K][256] -> hi/lo [256][K] -------
__global__ void wsplit_kernel(const float* __restrict__ W, int K,
                              unsigned short* __restrict__ hi,
                              unsigned short* __restrict__ lo) {
    int idx = blockIdx.x * blockDim.x + threadIdx.x;
    if (idx >= K * 256) return;
    int n = idx / K, k = idx % K;
    float a = W[(size_t)k * 256 + n];
    __nv_bfloat16 h = __float2bfloat16_rn(a);
    float hf = __bfloat162float(h);
    __nv_bfloat16 l = __float2bfloat16_rn(a - hf);
    hi[(size_t)n * K + k] = __bfloat16_as_ushort(h);
    lo[(size_t)n * K + k] = __bfloat16_as_ushort(l);
}

// ---------------- bf16x3 tensor-core GEMM machinery -------------------------
#define GBK 16
#define SM_STRIDE 48
#define BUF_BYTES 24576
#define OFF_ALO 6144
#define OFF_BHI 12288
#define OFF_BLO 18432

__device__ __forceinline__ void bsplit2(float a0, float a1,
                                        unsigned int& hi, unsigned int& lo) {
    __nv_bfloat16 h0 = __float2bfloat16_rn(a0);
    __nv_bfloat16 h1 = __float2bfloat16_rn(a1);
    float f0 = __bfloat162float(h0), f1 = __bfloat162float(h1);
    __nv_bfloat16 l0 = __float2bfloat16_rn(a0 - f0);
    __nv_bfloat16 l1 = __float2bfloat16_rn(a1 - f1);
    hi = (unsigned int)__bfloat16_as_ushort(h0) |
         ((unsigned int)__bfloat16_as_ushort(h1) << 16);
    lo = (unsigned int)__bfloat16_as_ushort(l0) |
         ((unsigned int)__bfloat16_as_ushort(l1) << 16);
}

// split 8 halves (uint4) into bf16 hi/lo packs — exact (11 bits -> 8 + 3)
__device__ __forceinline__ void hsplit8(uint4 v, uint4& hi, uint4& lo) {
    unsigned int* vi = (unsigned int*)&v;
    unsigned int* ho = (unsigned int*)&hi;
    unsigned int* lo_ = (unsigned int*)&lo;
#pragma unroll
    for (int q = 0; q < 4; q++) {
        float2 f = __half22float2(*(__half2*)&vi[q]);
        bsplit2(f.x, f.y, ho[q], lo_[q]);
    }
}

__device__ __forceinline__ void ldsm_x4(unsigned int addr, unsigned int* r) {
    asm volatile("ldmatrix.sync.aligned.m8n8.x4.shared.b16 {%0,%1,%2,%3}, [%4];"
                 : "=r"(r[0]), "=r"(r[1]), "=r"(r[2]), "=r"(r[3]) : "r"(addr));
}
__device__ __forceinline__ void ldsm_x2(unsigned int addr, unsigned int* r) {
    asm volatile("ldmatrix.sync.aligned.m8n8.x2.shared.b16 {%0,%1}, [%2];"
                 : "=r"(r[0]), "=r"(r[1]) : "r"(addr));
}
__device__ __forceinline__ void mma16816(float* c, const unsigned int* a,
                                         const unsigned int* b) {
    asm volatile(
        "mma.sync.aligned.m16n8k16.row.col.f32.bf16.bf16.f32 "
        "{%0,%1,%2,%3}, {%4,%5,%6,%7}, {%8,%9}, {%0,%1,%2,%3};"
        : "+f"(c[0]), "+f"(c[1]), "+f"(c[2]), "+f"(c[3])
        : "r"(a[0]), "r"(a[1]), "r"(a[2]), "r"(a[3]), "r"(b[0]), "r"(b[1]));
}

// core compute given smem tiles; shared by both GEMM variants via macro-free fn
struct GemmCtx {
    unsigned int sbase;
    int aRow, aKb, bRow, bKb;
};

__device__ __forceinline__ void gemm_mainchunk(
    const GemmCtx& cx, int buf, float acc[4][4][4])
{
    unsigned int base = cx.sbase + buf * BUF_BYTES;
    unsigned int aHi[4][4], aLo[4][4], bHi[4][2], bLo[4][2];
#pragma unroll
    for (int mt = 0; mt < 4; mt++) {
        unsigned int ra = base + (cx.aRow + mt * 16) * SM_STRIDE + cx.aKb;
        ldsm_x4(ra, aHi[mt]);
        ldsm_x4(ra + OFF_ALO, aLo[mt]);
    }
#pragma unroll
    for (int nt = 0; nt < 4; nt++) {
        unsigned int rb = base + OFF_BHI + (cx.bRow + nt * 8) * SM_STRIDE + cx.bKb;
        ldsm_x2(rb, bHi[nt]);
        ldsm_x2(rb + (OFF_BLO - OFF_BHI), bLo[nt]);
    }
#pragma unroll
    for (int mt = 0; mt < 4; mt++)
#pragma unroll
        for (int nt = 0; nt < 4; nt++) {
            mma16816(acc[mt][nt], aHi[mt], bHi[nt]);
            mma16816(acc[mt][nt], aHi[mt], bLo[nt]);
            mma16816(acc[mt][nt], aLo[mt], bHi[nt]);
        }
}

__device__ __forceinline__ void gemm_epilogue(
    float acc[4][4][4], __half* out, int m0, int n0, int wm, int wn, int lane)
{
    int cm = lane >> 2, cn = (lane & 3) * 2;
#pragma unroll
    for (int mt = 0; mt < 4; mt++) {
        int row = m0 + wm * 64 + mt * 16 + cm;
        float d1 = g_dis[row], d2 = g_dis[row + 8];
#pragma unroll
        for (int nt = 0; nt < 4; nt++) {
            int col = n0 + wn * 32 + nt * 8 + cn;
            __half2 h01 = __floats2half2_rn(d1 * acc[mt][nt][0], d1 * acc[mt][nt][1]);
            __half2 h23 = __floats2half2_rn(d2 * acc[mt][nt][2], d2 * acc[mt][nt][3]);
            *(__half2*)&out[(size_t)row * F + col]       = h01;
            *(__half2*)&out[(size_t)(row + 8) * F + col] = h23;
        }
    }
}

// ---- GEMM variant 1: A fp32 ------------------------------------------------
__global__ __launch_bounds__(256) void gemm_tc_f32_kernel(
    const float* __restrict__ A,
    const unsigned short* __restrict__ Whi,
    const unsigned short* __restrict__ Wlo,
    __half* __restrict__ out, int K)
{
    __shared__ __align__(16) unsigned char smem[2 * BUF_BYTES];
    int tid = threadIdx.x, lane = tid & 31, wid = tid >> 5;
    int wm = wid & 1, wn = wid >> 1;
    int m0 = blockIdx.y * 128, n0 = blockIdx.x * 128;

    float acc[4][4][4];
#pragma unroll
    for (int i = 0; i < 4; i++)
#pragma unroll
        for (int j = 0; j < 4; j++)
#pragma unroll
            for (int q = 0; q < 4; q++) acc[i][j][q] = 0.f;

    int am[2], akq[2];
    am[0] = tid >> 2;           akq[0] = tid & 3;
    am[1] = (tid + 256) >> 2;   akq[1] = (tid + 256) & 3;
    int bn = tid >> 1, bc = tid & 1;

    const int niter = K / GBK;
    float4 stA[2];

#pragma unroll
    for (int t = 0; t < 2; t++)
        stA[t] = *(const float4*)&A[(size_t)(m0 + am[t]) * K + akq[t] * 4];
    cp_async16(smem + OFF_BHI + bn * SM_STRIDE + bc * 16, &Whi[(size_t)(n0 + bn) * K + bc * 8]);
    cp_async16(smem + OFF_BLO + bn * SM_STRIDE + bc * 16, &Wlo[(size_t)(n0 + bn) * K + bc * 8]);
    asm volatile("cp.async.commit_group;" ::: "memory");
#pragma unroll
    for (int t = 0; t < 2; t++) {
        unsigned int h01, l01, h23, l23;
        bsplit2(stA[t].x, stA[t].y, h01, l01);
        bsplit2(stA[t].z, stA[t].w, h23, l23);
        *(uint2*)(smem + am[t] * SM_STRIDE + akq[t] * 8) = make_uint2(h01, h23);
        *(uint2*)(smem + OFF_ALO + am[t] * SM_STRIDE + akq[t] * 8) = make_uint2(l01, l23);
    }
    asm volatile("cp.async.wait_group 0;" ::: "memory");
    __syncthreads();

    GemmCtx cx;
    cx.sbase = (unsigned int)__cvta_generic_to_shared(smem);
    cx.aRow = wm * 64 + ((lane >> 3) & 1) * 8 + (lane & 7);
    cx.aKb  = (lane >> 4) * 16;
    cx.bRow = wn * 32 + ((lane & 15) & 7);
    cx.bKb  = ((lane & 15) >> 3) * 16;

    int buf = 0;
    for (int it = 0; it < niter; it++) {
        if (it + 1 < niter) {
#pragma unroll
            for (int t = 0; t < 2; t++)
                stA[t] = *(const float4*)&A[(size_t)(m0 + am[t]) * K + (it + 1) * GBK + akq[t] * 4];
            unsigned char* nb = smem + (buf ^ 1) * BUF_BYTES;
            cp_async16(nb + OFF_BHI + bn * SM_STRIDE + bc * 16,
                       &Whi[(size_t)(n0 + bn) * K + (it + 1) * GBK + bc * 8]);
            cp_async16(nb + OFF_BLO + bn * SM_STRIDE + bc * 16,
                       &Wlo[(size_t)(n0 + bn) * K + (it + 1) * GBK + bc * 8]);
            asm volatile("cp.async.commit_group;" ::: "memory");
        }
        gemm_mainchunk(cx, buf, acc);
        if (it + 1 < niter) {
            unsigned char* nb = smem + (buf ^ 1) * BUF_BYTES;
#pragma unroll
            for (int t = 0; t < 2; t++) {
                unsigned int h01, l01, h23, l23;
                bsplit2(stA[t].x, stA[t].y, h01, l01);
                bsplit2(stA[t].z, stA[t].w, h23, l23);
                *(uint2*)(nb + am[t] * SM_STRIDE + akq[t] * 8) = make_uint2(h01, h23);
                *(uint2*)(nb + OFF_ALO + am[t] * SM_STRIDE + akq[t] * 8) = make_uint2(l01, l23);
            }
            asm volatile("cp.async.wait_group 0;" ::: "memory");
        }
        __syncthreads();
        buf ^= 1;
    }
    gemm_epilogue(acc, out, m0, n0, wm, wn, lane);
}

// ---- GEMM variant 2: A fp16 (exact hi/lo split) ----------------------------
__global__ __launch_bounds__(256) void gemm_tc_f16_kernel(
    const __half* __restrict__ A,
    const unsigned short* __restrict__ Whi,
    const unsigned short* __restrict__ Wlo,
    __half* __restrict__ out, int K)
{
    __shared__ __align__(16) unsigned char smem[2 * BUF_BYTES];
    int tid = threadIdx.x, lane = tid & 31, wid = tid >> 5;
    int wm = wid & 1, wn = wid >> 1;
    int m0 = blockIdx.y * 128, n0 = blockIdx.x * 128;

    float acc[4][4][4];
#pragma unroll
    for (int i = 0; i < 4; i++)
#pragma unroll
        for (int j = 0; j < 4; j++)
#pragma unroll
            for (int q = 0; q < 4; q++) acc[i][j][q] = 0.f;

    int ar = tid >> 1, ac = tid & 1;   // row, 8-half chunk
    int bn = tid >> 1, bc = tid & 1;

    const int niter = K / GBK;
    uint4 stA;

    stA = *(const uint4*)&A[(size_t)(m0 + ar) * K + ac * 8];
    cp_async16(smem + OFF_BHI + bn * SM_STRIDE + bc * 16, &Whi[(size_t)(n0 + bn) * K + bc * 8]);
    cp_async16(smem + OFF_BLO + bn * SM_STRIDE + bc * 16, &Wlo[(size_t)(n0 + bn) * K + bc * 8]);
    asm volatile("cp.async.commit_group;" ::: "memory");
    {
        uint4 hi, lo;
        hsplit8(stA, hi, lo);
        *(uint4*)(smem + ar * SM_STRIDE + ac * 16) = hi;
        *(uint4*)(smem + OFF_ALO + ar * SM_STRIDE + ac * 16) = lo;
    }
    asm volatile("cp.async.wait_group 0;" ::: "memory");
    __syncthreads();

    GemmCtx cx;
    cx.sbase = (unsigned int)__cvta_generic_to_shared(smem);
    cx.aRow = wm * 64 + ((lane >> 3) & 1) * 8 + (lane & 7);
    cx.aKb  = (lane >> 4) * 16;
    cx.bRow = wn * 32 + ((lane & 15) & 7);
    cx.bKb  = ((lane & 15) >> 3) * 16;

    int buf = 0;
    for (int it = 0; it < niter; it++) {
        if (it + 1 < niter) {
            stA = *(const uint4*)&A[(size_t)(m0 + ar) * K + (it + 1) * GBK + ac * 8];
            unsigned char* nb = smem + (buf ^ 1) * BUF_BYTES;
            cp_async16(nb + OFF_BHI + bn * SM_STRIDE + bc * 16,
                       &Whi[(size_t)(n0 + bn) * K + (it + 1) * GBK + bc * 8]);
            cp_async16(nb + OFF_BLO + bn * SM_STRIDE + bc * 16,
                       &Wlo[(size_t)(n0 + bn) * K + (it + 1) * GBK + bc * 8]);
            asm volatile("cp.async.commit_group;" ::: "memory");
        }
        gemm_mainchunk(cx, buf, acc);
        if (it + 1 < niter) {
            unsigned char* nb = smem + (buf ^ 1) * BUF_BYTES;
            uint4 hi, lo;
            hsplit8(stA, hi, lo);
            *(uint4*)(nb + ar * SM_STRIDE + ac * 16) = hi;
            *(uint4*)(nb + OFF_ALO + ar * SM_STRIDE + ac * 16) = lo;
            asm volatile("cp.async.wait_group 0;" ::: "memory");
        }
        __syncthreads();
        buf ^= 1;
    }
    gemm_epilogue(acc, out, m0, n0, wm, wn, lane);
}

// ---------------- Aggregation: warp per destination node --------------------
// out16[dst] = act( dis[dst] * (sum_{src} hps[src] + hps[dst]) + b )
__device__ __forceinline__ void acc8(float* a, uint4 v) {
    float2 f0 = __half22float2(*(__half2*)&v.x);
    float2 f1 = __half22float2(*(__half2*)&v.y);
    float2 f2 = __half22float2(*(__half2*)&v.z);
    float2 f3 = __half22float2(*(__half2*)&v.w);
    a[0] += f0.x; a[1] += f0.y; a[2] += f1.x; a[3] += f1.y;
    a[4] += f2.x; a[5] += f2.y; a[6] += f3.x; a[7] += f3.y;
}

__global__ __launch_bounds__(256) void agg_kernel(
    const __half* __restrict__ hp, const float* __restrict__ bias,
    __half* __restrict__ out, int relu)
{
    int warp = (blockIdx.x * blockDim.x + threadIdx.x) >> 5;
    if (warp >= N_TOTAL) return;
    int lane = threadIdx.x & 31;
    const uint4* hp4 = (const uint4*)hp;   // 8 halves per uint4; 32 per row
    int dst = warp;

    float a[8];
    {
        uint4 v = hp4[(size_t)dst * 32 + lane];
        float2 f0 = __half22float2(*(__half2*)&v.x);
        float2 f1 = __half22float2(*(__half2*)&v.y);
        float2 f2 = __half22float2(*(__half2*)&v.z);
        float2 f3 = __half22float2(*(__half2*)&v.w);
        a[0] = f0.x; a[1] = f0.y; a[2] = f1.x; a[3] = f1.y;
        a[4] = f2.x; a[5] = f2.y; a[6] = f3.x; a[7] = f3.y;
    }

    int e = g_rowptr[dst], end = g_rowptr[dst + 1];
    for (; e + 4 <= end; e += 4) {
        int s0 = g_col[e], s1 = g_col[e + 1], s2 = g_col[e + 2], s3 = g_col[e + 3];
        uint4 v0 = hp4[(size_t)s0 * 32 + lane];
        uint4 v1 = hp4[(size_t)s1 * 32 + lane];
        uint4 v2 = hp4[(size_t)s2 * 32 + lane];
        uint4 v3 = hp4[(size_t)s3 * 32 + lane];
        acc8(a, v0); acc8(a, v1); acc8(a, v2); acc8(a, v3);
    }
    for (; e < end; e++) {
        uint4 v0 = hp4[(size_t)g_col[e] * 32 + lane];
        acc8(a, v0);
    }

    float dd = g_dis[dst];
    const float4* b4 = (const float4*)bias;
    float4 b0 = b4[lane * 2], b1 = b4[lane * 2 + 1];
    float r[8];
    r[0] = fmaf(dd, a[0], b0.x); r[1] = fmaf(dd, a[1], b0.y);
    r[2] = fmaf(dd, a[2], b0.z); r[3] = fmaf(dd, a[3], b0.w);
    r[4] = fmaf(dd, a[4], b1.x); r[5] = fmaf(dd, a[5], b1.y);
    r[6] = fmaf(dd, a[6], b1.z); r[7] = fmaf(dd, a[7], b1.w);
    if (relu) {
#pragma unroll
        for (int j = 0; j < 8; j++) r[j] = fmaxf(r[j], 0.f);
    }
    uint4 o;
    *(__half2*)&o.x = __floats2half2_rn(r[0], r[1]);
    *(__half2*)&o.y = __floats2half2_rn(r[2], r[3]);
    *(__half2*)&o.z = __floats2half2_rn(r[4], r[5]);
    *(__half2*)&o.w = __floats2half2_rn(r[6], r[7]);
    ((uint4*)out)[(size_t)dst * 32 + lane] = o;
}

// ---------------- readout (meanmax, fp16 in) + final linear -----------------
__global__ __launch_bounds__(256) void readout_kernel(
    const __half* __restrict__ h, const float* __restrict__ Wm,
    const float* __restrict__ bm, float* __restrict__ out)
{
    int g = blockIdx.x;
    int t = threadIdx.x;
    const __half* base = h + (size_t)g * NODES_PER_G * F;
    float s = 0.f, mx = -INFINITY;
    for (int i = 0; i < NODES_PER_G; i++) {
        float v = __half2float(base[(size_t)i * F + t]);
        s += v;
        mx = fmaxf(mx, v);
    }
    __shared__ float gf[2 * F];
    gf[t]     = s * (1.0f / NODES_PER_G);
    gf[F + t] = mx;
    __syncthreads();

    float p0 = gf[t] * Wm[t * 2 + 0] + gf[F + t] * Wm[(F + t) * 2 + 0];
    float p1 = gf[t] * Wm[t * 2 + 1] + gf[F + t] * Wm[(F + t) * 2 + 1];
    __shared__ float r0[256], r1[256];
    r0[t] = p0; r1[t] = p1;
    __syncthreads();
    for (int off = 128; off > 0; off >>= 1) {
        if (t < off) { r0[t] += r0[t + off]; r1[t] += r1[t + off]; }
        __syncthreads();
    }
    if (t == 0) {
        out[g * 2 + 0] = r0[0] + bm[0];
        out[g * 2 + 1] = r1[0] + bm[1];
    }
}

// ---------------- launcher --------------------------------------------------
extern "C" void kernel_launch(void* const* d_in, const int* in_sizes, int n_in,
                              void* d_out, int out_size)
{
    int base = (in_sizes[3] == 1) ? 4 : 3;
    const float* x  = (const float*)d_in[0];
    const void*  ei = d_in[1];
    const float* W1 = (const float*)d_in[base + 0];
    const float* b1 = (const float*)d_in[base + 1];
    const float* W2 = (const float*)d_in[base + 2];
    const float* b2 = (const float*)d_in[base + 3];
    const float* Wm = (const float*)d_in[base + 4];
    const float* bm = (const float*)d_in[base + 5];
    float* out = (float*)d_out;

    __half *hps = nullptr, *p16 = nullptr;
    unsigned short *w1hi, *w1lo, *w2hi, *w2lo;
    cudaGetSymbolAddress((void**)&hps, g_hps);
    cudaGetSymbolAddress((void**)&p16, g_p16);
    cudaGetSymbolAddress((void**)&w1hi, g_w1hi);
    cudaGetSymbolAddress((void**)&w1lo, g_w1lo);
    cudaGetSymbolAddress((void**)&w2hi, g_w2hi);
    cudaGetSymbolAddress((void**)&w2lo, g_w2lo);

    const int TB = 256;
    dim3 gg(2, N_TOTAL / 128);   // (N tiles, M tiles)

    init_kernel<<<N_TOTAL / TB, TB>>>();
    detect_kernel<<<1, 1024>>>((const unsigned int*)ei);
    count_kernel<<<(E_TOTAL / 2 + TB - 1) / TB, TB>>>(ei);
    scan1_kernel<<<400, 256>>>();
    scan2_kernel<<<1, 512>>>();
    scan3_kernel<<<400, 256>>>();
    fill_kernel<<<(E_TOTAL / 2 + TB - 1) / TB, TB>>>(ei);
    wsplit_kernel<<<(400 * 256 + TB - 1) / TB, TB>>>(W1, 400, w1hi, w1lo);
    wsplit_kernel<<<(256 * 256 + TB - 1) / TB, TB>>>(W2, 256, w2hi, w2lo);
    // gemm1: hps = fp16(dis * (x @ W1))
    gemm_tc_f32_kernel<<<gg, 256>>>(x, w1hi, w1lo, hps, 400);
    // agg1: p16 = fp16(relu(dis*(sum hps) + b1))
    agg_kernel<<<N_TOTAL / 8, 256>>>(hps, b1, p16, 1);
    // gemm2: hps = fp16(dis * (p16 @ W2))
    gemm_tc_f16_kernel<<<gg, 256>>>(p16, w2hi, w2lo, hps, 256);
    // agg2: p16 = fp16(dis*(sum hps) + b2)
    agg_kernel<<<N_TOTAL / 8, 256>>>(hps, b2, p16, 0);
    readout_kernel<<<NUM_G, 256>>>(p16, Wm, bm, out);
}